// round 16
// baseline (speedup 1.0000x reference)
#include <cuda_runtime.h>
#include <cuda_bf16.h>

#define NHEADS 512
#define NK     64
#define SEQ    2048
#define NFFT   4096
#define NB     16
#define PITCH  272   // FFT transpose pitch: 16*17, conflict-free both patterns

typedef unsigned long long ull;

// Scratch (static __device__ — no allocation)
__device__ float d_f[NHEADS * SEQ];       // filter taps (1/NFFT folded)
__device__ ull   d_Fhat[NHEADS * NFFT];   // packed complex, layout [h][q*256+t]
__device__ ull   d_T1[16 * 256];          // exp(-2*pi*i*q*t/4096)
__device__ ull   d_T2[16 * 16];           // exp(-2*pi*i*q*o/256)

// ---------------------------------------------------------------------------
// Packed f32x2 complex helpers (value = ull, lo 32b = re, hi 32b = im)
// ---------------------------------------------------------------------------
__device__ __forceinline__ ull pk2(float x, float y) {
    ull r; asm("mov.b64 %0, {%1, %2};" : "=l"(r) : "f"(x), "f"(y)); return r;
}
__device__ __forceinline__ void unpk2(ull a, float& x, float& y) {
    asm("mov.b64 {%0, %1}, %2;" : "=f"(x), "=f"(y) : "l"(a));
}
__device__ __forceinline__ ull padd(ull a, ull b) {
    ull r; asm("add.rn.f32x2 %0, %1, %2;" : "=l"(r) : "l"(a), "l"(b)); return r;
}
__device__ __forceinline__ ull psub(ull a, ull b) {   // a - b via fma(b, -1, a)
    const ull m1 = 0xBF800000BF800000ULL;
    ull r; asm("fma.rn.f32x2 %0, %1, %2, %3;" : "=l"(r) : "l"(b), "l"(m1), "l"(a)); return r;
}
__device__ __forceinline__ float fneg(float x) {
    return __int_as_float(__float_as_int(x) ^ 0x80000000);
}
template<int INV>
__device__ __forceinline__ ull pmulj(ull a) {
    float x, y; unpk2(a, x, y);
    return INV ? pk2(fneg(y), x) : pk2(y, fneg(x));
}
__device__ __forceinline__ ull pcmulf(ull a, float wx, float wy) {
    float x, y; unpk2(a, x, y);
    return pk2(fmaf(x, wx, -(y * wy)), fmaf(x, wy, y * wx));
}

template<int INV>
__device__ __forceinline__ void bfly4p(ull& x0, ull& x1, ull& x2, ull& x3) {
    ull ac = padd(x0, x2), amc = psub(x0, x2);
    ull bd = padd(x1, x3), bmd = psub(x1, x3);
    ull jb = pmulj<INV>(bmd);
    x0 = padd(ac, bd);  x2 = psub(ac, bd);
    x1 = padd(amc, jb); x3 = psub(amc, jb);
}

// half-output butterfly: only out0/out1 produced
template<int INV>
__device__ __forceinline__ void bfly4p_half(ull& x0, ull& x1, ull x2, ull x3) {
    ull ac = padd(x0, x2), amc = psub(x0, x2);
    ull bd = padd(x1, x3), bmd = psub(x1, x3);
    ull jb = pmulj<INV>(bmd);
    x0 = padd(ac, bd);
    x1 = padd(amc, jb);
}

template<int INV>
__device__ __forceinline__ void tw16(ull* u) {
    const float C1 = 0.9238795325112867f, S1 = 0.3826834323650898f, R = 0.7071067811865476f;
    const float s = INV ? 1.0f : -1.0f;
    u[5]  = pcmulf(u[5],   C1,  s * S1);
    u[6]  = pcmulf(u[6],    R,  s * R);
    u[7]  = pcmulf(u[7],   S1,  s * C1);
    u[9]  = pcmulf(u[9],    R,  s * R);
    u[10] = pmulj<INV>(u[10]);
    u[11] = pcmulf(u[11],  -R,  s * R);
    u[13] = pcmulf(u[13],  S1,  s * C1);
    u[14] = pcmulf(u[14],  -R,  s * R);
    u[15] = pcmulf(u[15], -C1, -s * S1);
}

template<int INV>
__device__ __forceinline__ void dft16p(ull* x) {
    ull u[16];
    #pragma unroll
    for (int n1 = 0; n1 < 4; n1++) {
        ull a = x[n1], b = x[n1 + 4], c = x[n1 + 8], d = x[n1 + 12];
        bfly4p<INV>(a, b, c, d);
        u[n1 * 4 + 0] = a; u[n1 * 4 + 1] = b; u[n1 * 4 + 2] = c; u[n1 * 4 + 3] = d;
    }
    tw16<INV>(u);
    #pragma unroll
    for (int k1 = 0; k1 < 4; k1++) {
        ull a = u[k1], b = u[4 + k1], c = u[8 + k1], d = u[12 + k1];
        bfly4p<INV>(a, b, c, d);
        x[k1] = a; x[k1 + 4] = b; x[k1 + 8] = c; x[k1 + 12] = d;
    }
}

// Inverse 16-pt DFT producing only outputs 0..7 (final inv stage).
__device__ __forceinline__ void dft16p_half(ull* x) {
    ull u[16];
    #pragma unroll
    for (int n1 = 0; n1 < 4; n1++) {
        ull a = x[n1], b = x[n1 + 4], c = x[n1 + 8], d = x[n1 + 12];
        bfly4p<1>(a, b, c, d);
        u[n1 * 4 + 0] = a; u[n1 * 4 + 1] = b; u[n1 * 4 + 2] = c; u[n1 * 4 + 3] = d;
    }
    tw16<1>(u);
    #pragma unroll
    for (int k1 = 0; k1 < 4; k1++) {
        ull a = u[k1], b = u[4 + k1];
        bfly4p_half<1>(a, b, u[8 + k1], u[12 + k1]);
        x[k1] = a; x[k1 + 4] = b;
    }
}

// Forward 16-pt DFT with x[8..15] == 0 (only x[0..7] read; all 16 written).
__device__ __forceinline__ void dft16ph(ull* x) {
    ull u[16];
    #pragma unroll
    for (int n1 = 0; n1 < 4; n1++) {
        ull a = x[n1], b = x[n1 + 4];      // c = d = 0
        ull jb = pmulj<0>(b);
        u[n1 * 4 + 0] = padd(a, b);
        u[n1 * 4 + 2] = psub(a, b);
        u[n1 * 4 + 1] = padd(a, jb);
        u[n1 * 4 + 3] = psub(a, jb);
    }
    tw16<0>(u);
    #pragma unroll
    for (int k1 = 0; k1 < 4; k1++) {
        ull a = u[k1], b = u[4 + k1], c = u[8 + k1], d = u[12 + k1];
        bfly4p<0>(a, b, c, d);
        x[k1] = a; x[k1 + 4] = b; x[k1 + 8] = c; x[k1 + 12] = d;
    }
}

// ---------------------------------------------------------------------------
// N=4096 radix-16 FFT with table twiddles (tables filled by filter_kernel).
// FWD=1: use T as-is; FWD=0 (inverse): conjugate on the fly.
// ---------------------------------------------------------------------------
template<int FWD>
__device__ __forceinline__ void twtab1(ull* r, int t) {
    #pragma unroll
    for (int q = 1; q < 16; q++) {
        float wx, wy; unpk2(__ldg(&d_T1[q * 256 + t]), wx, wy);
        r[q] = pcmulf(r[q], wx, FWD ? wy : fneg(wy));
    }
}
template<int FWD>
__device__ __forceinline__ void twtab2(ull* r, int o) {
    #pragma unroll
    for (int q = 1; q < 16; q++) {
        float wx, wy; unpk2(__ldg(&d_T2[q * 16 + o]), wx, wy);
        r[q] = pcmulf(r[q], wx, FWD ? wy : fneg(wy));
    }
}

__device__ __forceinline__ void fft4096_fwd(ull* r, ull* sh, int t) {
    const int o = t & 15, b = t >> 4;
    dft16ph(r);
    twtab1<1>(r, t);
    #pragma unroll
    for (int q = 0; q < 16; q++) sh[PITCH * q + t] = r[q];
    __syncthreads();
    #pragma unroll
    for (int m = 0; m < 16; m++) r[m] = sh[PITCH * b + 16 * m + o];
    dft16p<0>(r);
    twtab2<1>(r, o);
    __syncthreads();
    #pragma unroll
    for (int q = 0; q < 16; q++) sh[PITCH * b + 17 * q + o] = r[q];
    __syncthreads();
    #pragma unroll
    for (int j = 0; j < 16; j++) r[j] = sh[PITCH * b + 17 * o + j];
    dft16p<0>(r);
}

__device__ __forceinline__ void fft4096_inv(ull* r, ull* sh, int t) {
    const int o = t & 15, b = t >> 4;
    dft16p<1>(r);
    __syncthreads();
    #pragma unroll
    for (int j = 0; j < 16; j++) sh[PITCH * b + 17 * o + j] = r[j];
    __syncthreads();
    #pragma unroll
    for (int q = 0; q < 16; q++) r[q] = sh[PITCH * b + 17 * q + o];
    twtab2<0>(r, o);
    dft16p<1>(r);
    __syncthreads();
    #pragma unroll
    for (int m = 0; m < 16; m++) sh[PITCH * b + 16 * m + o] = r[m];
    __syncthreads();
    #pragma unroll
    for (int q = 0; q < 16; q++) r[q] = sh[PITCH * q + t];
    twtab1<0>(r, t);
    dft16p_half(r);
}

// ---------------------------------------------------------------------------
// K1: TWO heads per block (512 threads).  Per head (256 threads):
//   doubling impulse response (validated R15) + phase C streaming FIR -> d_f.
// Blocks 0..15 additionally fill the twiddle tables (exact sincospif).
// ---------------------------------------------------------------------------
__global__ __launch_bounds__(512) void filter_kernel(const float* __restrict__ kin) {
    __shared__ float sw[2][128];          // w padded: sw[hf][64..127] = 0
    __shared__ float sg[2][64], skn[2][64], sP[2][64], spart[2][2];
    __shared__ float po[2][64];
    __shared__ float OO[2][128];
    __shared__ float hp[2][64 + SEQ];

    const int tid = threadIdx.x;
    const int hf  = tid >> 8;          // half index: which head in this block
    const int t   = tid & 255;
    const int hh  = blockIdx.x * 2 + hf;

    // ---- twiddle-table fill (blocks 0..15; row q = blockIdx.x)
    if (blockIdx.x < 16) {
        const int q = blockIdx.x;
        if (tid < 256) {
            float s, c;
            sincospif(-(float)(q * tid) / 2048.0f, &s, &c);
            d_T1[q * 256 + tid] = pk2(c, s);
        } else if (tid < 256 + 16) {
            const int o = tid - 256;
            float s, c;
            sincospif(-(float)(q * o) / 128.0f, &s, &c);
            d_T2[q * 16 + o] = pk2(c, s);
        }
    }

    for (int i = t; i < 64 + SEQ; i += 256) hp[hf][i] = 0.f;
    if (t < 128) { sw[hf][t] = 0.f; OO[hf][t] = 0.f; }
    if (t < 64)  po[hf][t] = 0.f;

    // ---- prep: kn, P, w, g (threads t<64 of each half)
    float kv = 0.f;
    if (t < 64) {
        kv = kin[hh * NK + t];
        float kc = fminf(fmaxf(kv, 0.0625f), 1.0f);
        float v = kc;
        #pragma unroll
        for (int o = 16; o; o >>= 1) v += __shfl_xor_sync(0xffffffffu, v, o);
        if ((t & 31) == 0) spart[hf][t >> 5] = v;
        skn[hf][t] = kc;
    }
    __syncthreads();
    if (t < 64) skn[hf][t] = skn[hf][t] / (spart[hf][0] + spart[hf][1]);
    __syncthreads();
    if (t == 0) {
        float pr = 1.0f;
        for (int j = 0; j < 64; j++) {
            sP[hf][j] = pr;
            if (j < 63) pr *= 1.0f / (1.0f + skn[hf][j]);
        }
        hp[hf][64] = 1.0f;   // h_0
    }
    __syncthreads();
    if (t < 64) {
        float kn = skn[hf][t];
        float m0 = (t < 63) ? kn / (1.0f + kn) : 1.0f;
        sw[hf][t] = m0 * sP[hf][t];
        sg[hf][t] = kv * sP[hf][t] * (1.0f / NFFT);
    }
    __syncthreads();

    // ---- warp bootstrap h_1..63 (first warp of each half; validated)
    if (t < 32) {
        const int rr = t;
        #pragma unroll
        for (int s = 1; s <= 32; s <<= 1) {
            float oc = 0.f;
            if (rr < s) {
                #pragma unroll
                for (int m = 0; m < 32; m++)
                    oc += sw[hf][rr + m] * hp[hf][64 + s - 1 - m];
                po[hf][32 + rr] = oc;
            }
            __syncwarp();
            if (rr < s) {
                float nv = 0.f;
                #pragma unroll
                for (int d = 0; d < 32; d++)
                    nv += hp[hf][64 + d] * po[hf][32 + rr - d];
                hp[hf][64 + s + rr] = nv;
            }
            __syncwarp();
        }
    }
    __syncthreads();

    // ---- block levels s = 64, 128, 256 (plain per-output; validated)
    for (int s = 64; s <= 256; s <<= 1) {
        if (t < 64) {
            const float* base = &hp[hf][64 + s + t - 1];
            float a0 = 0.f, a1 = 0.f, a2 = 0.f, a3 = 0.f;
            #pragma unroll
            for (int i = 0; i < 64; i += 4) {
                a0 += sw[hf][i + 0] * base[-i - 0];
                a1 += sw[hf][i + 1] * base[-i - 1];
                a2 += sw[hf][i + 2] * base[-i - 2];
                a3 += sw[hf][i + 3] * base[-i - 3];
            }
            OO[hf][64 + t] = (a0 + a1) + (a2 + a3);
        }
        __syncthreads();
        for (int r = t; r < s; r += 256) {
            const float* hb = &hp[hf][64 + r];
            float a0 = 0.f, a1 = 0.f, a2 = 0.f, a3 = 0.f;
            #pragma unroll
            for (int m = 0; m < 64; m += 4) {
                a0 += OO[hf][64 + m + 0] * hb[-m - 0];
                a1 += OO[hf][64 + m + 1] * hb[-m - 1];
                a2 += OO[hf][64 + m + 2] * hb[-m - 2];
                a3 += OO[hf][64 + m + 3] * hb[-m - 3];
            }
            hp[hf][64 + s + r] = (a0 + a1) + (a2 + a3);
        }
        __syncthreads();
    }

    // ---- levels s = 512, 1024 (streaming FIR; validated R15)
    for (int s = 512; s <= 1024; s <<= 1) {
        if (t < 64) {
            const float* base = &hp[hf][64 + s + t - 1];
            float a0 = 0.f, a1 = 0.f, a2 = 0.f, a3 = 0.f;
            #pragma unroll
            for (int i = 0; i < 64; i += 4) {
                a0 += sw[hf][i + 0] * base[-i - 0];
                a1 += sw[hf][i + 1] * base[-i - 1];
                a2 += sw[hf][i + 2] * base[-i - 2];
                a3 += sw[hf][i + 3] * base[-i - 3];
            }
            OO[hf][64 + t] = (a0 + a1) + (a2 + a3);
        }
        __syncthreads();
        {
            const int r0 = t * 8;
            if (r0 < s) {
                float acc[8];
                #pragma unroll
                for (int k = 0; k < 8; k++) acc[k] = 0.f;
                #pragma unroll
                for (int mc = 0; mc < 8; mc++) {
                    float w[15];
                    const int base = 64 + r0 - 8 * mc - 7;   // >= 1, pad-safe
                    #pragma unroll
                    for (int d = 0; d < 15; d++) w[d] = hp[hf][base + d];
                    #pragma unroll
                    for (int j = 0; j < 8; j++) {
                        const float c = OO[hf][64 + 8 * mc + j];
                        #pragma unroll
                        for (int k = 0; k < 8; k++)
                            acc[k] += c * w[7 + k - j];
                    }
                }
                #pragma unroll
                for (int k = 0; k < 8; k++)
                    hp[hf][64 + s + r0 + k] = acc[k];
            }
        }
        __syncthreads();
    }

    // ---- phase C: f = g conv h (streaming FIR, pad-safe) -> d_f
    {
        const int t0 = t * 8;
        float acc[8];
        #pragma unroll
        for (int k = 0; k < 8; k++) acc[k] = 0.f;
        #pragma unroll
        for (int ic = 0; ic < 8; ic++) {
            float w[15];
            const int base = 64 + t0 - 8 * ic - 7;   // >= 1, zero pad covers t<63
            #pragma unroll
            for (int d = 0; d < 15; d++) w[d] = hp[hf][base + d];
            #pragma unroll
            for (int j = 0; j < 8; j++) {
                const float g = sg[hf][8 * ic + j];
                #pragma unroll
                for (int k = 0; k < 8; k++)
                    acc[k] += g * w[7 + k - j];
            }
        }
        #pragma unroll
        for (int k = 0; k < 8; k++)
            d_f[hh * SEQ + t0 + k] = acc[k];
    }
}

// ---------------------------------------------------------------------------
// K2: filter spectrum (packed), layout [h][q*256+t]; 1/N folded into d_f.
// ---------------------------------------------------------------------------
__global__ __launch_bounds__(256) void fft_filter_kernel() {
    __shared__ ull exch[16 * PITCH];
    ull r[16];
    const int t = threadIdx.x, h = blockIdx.x;

    #pragma unroll
    for (int q = 0; q < 8; q++)
        r[q] = pk2(d_f[h * SEQ + t + 256 * q], 0.f);

    fft4096_fwd(r, exch, t);

    #pragma unroll
    for (int q = 0; q < 16; q++)
        d_Fhat[(size_t)h * NFFT + q * 256 + t] = r[q];
}

// ---------------------------------------------------------------------------
// K3: FFT convolution, two batches packed per complex FFT.
// ---------------------------------------------------------------------------
__global__ __launch_bounds__(256, 4) void conv_kernel(const float* __restrict__ u,
                                                      float* __restrict__ y) {
    __shared__ ull exch[16 * PITCH];
    ull r[16];
    const int t  = threadIdx.x;
    const int h  = blockIdx.y;
    const int bp = blockIdx.x;
    const float* u0 = u + ((size_t)(2 * bp) * NHEADS + h) * SEQ;
    const float* u1 = u0 + (size_t)NHEADS * SEQ;

    #pragma unroll
    for (int q = 0; q < 8; q++) {
        int idx = t + 256 * q;
        r[q] = pk2(__ldg(&u0[idx]), __ldg(&u1[idx]));
    }

    fft4096_fwd(r, exch, t);

    const ull* Fh = d_Fhat + (size_t)h * NFFT;
    #pragma unroll
    for (int q = 0; q < 16; q++) {
        float fx, fy; unpk2(__ldg(&Fh[q * 256 + t]), fx, fy);
        r[q] = pcmulf(r[q], fx, fy);
    }

    fft4096_inv(r, exch, t);

    float* y0 = y + ((size_t)(2 * bp) * NHEADS + h) * SEQ;
    float* y1 = y0 + (size_t)NHEADS * SEQ;
    #pragma unroll
    for (int m = 0; m < 8; m++) {
        int idx = t + 256 * m;
        float a, b; unpk2(r[m], a, b);
        y0[idx] = a;
        y1[idx] = b;
    }
}

// ---------------------------------------------------------------------------
extern "C" void kernel_launch(void* const* d_in, const int* in_sizes, int n_in,
                              void* d_out, int out_size) {
    const float* u = (const float*)d_in[0];
    const float* k = (const float*)d_in[1];
    if (n_in >= 2 && in_sizes[0] < in_sizes[1]) {
        const float* t = u; u = k; k = t;
    }
    float* y = (float*)d_out;

    filter_kernel<<<NHEADS / 2, 512>>>(k);
    fft_filter_kernel<<<NHEADS, 256>>>();
    conv_kernel<<<dim3(NB / 2, NHEADS), 256>>>(u, y);
}